// round 8
// baseline (speedup 1.0000x reference)
#include <cuda_runtime.h>
#include <cuda_fp16.h>
#include <stdint.h>

#define KD 768
#define ND 768

#define BM 128
#define BN 128
#define BK 64
#define KTILES (KD / BK)                // 12
#define NSTG 3
#define STG_BYTES (BM * BK + BN * BK)   // 16384
#define NBLK_N (ND / BN)                // 6
#define NCONV 148
#define WTILES ((ND / 32) * (KD / 32))  // 576

// Scratch (device globals — no runtime allocation).
__device__ int8_t g_X8[(size_t)32768 * KD];
__device__ int8_t g_Wt[ND * KD];
__device__ int    g_modes[3];
__device__ int    g_flag[512];          // per-128-row-chunk ready flags
__device__ int    g_wcnt;               // weight tiles done

// ===========================================================================
// acquire/release helpers
// ===========================================================================
__device__ __forceinline__ int ld_acq(const int* p) {
    int v;
    asm volatile("ld.global.acquire.gpu.b32 %0, [%1];" : "=r"(v) : "l"(p));
    return v;
}
__device__ __forceinline__ void st_rel(int* p, int v) {
    asm volatile("st.global.release.gpu.b32 [%0], %1;" :: "l"(p), "r"(v));
}

// ===========================================================================
// dtype detection (x/w: 0=f32-of-ints, 1=int32, 2=int8; bias: 0=f32, 1=f16)
// Also resets the producer/consumer flags each launch (graph-replay safe).
// ===========================================================================
__device__ __forceinline__ bool ok_f32_int(uint32_t u) {
    float f = __uint_as_float(u);
    return isfinite(f) && f == rintf(f) && fabsf(f) <= 127.f;
}
__device__ __forceinline__ bool ok_i32(uint32_t u) {
    int v = (int)u;
    return v >= -128 && v <= 127;
}

__global__ void detect(const uint32_t* __restrict__ x,
                       const uint32_t* __restrict__ w,
                       const uint32_t* __restrict__ b) {
    __shared__ int cnt[6];
    const int tid = threadIdx.x;
    if (tid < 6) cnt[tid] = 0;
    g_flag[tid] = 0;
    g_flag[tid + 256] = 0;
    if (tid == 0) g_wcnt = 0;
    __syncthreads();

    int xf = 0, xi = 0, wf = 0, wi = 0;
#pragma unroll 4
    for (int i = 0; i < 16; i++) {
        uint32_t ux = x[tid * 16 + i];
        uint32_t uw = w[tid * 16 + i];
        xf += ok_f32_int(ux);  xi += ok_i32(ux);
        wf += ok_f32_int(uw);  wi += ok_i32(uw);
    }
    atomicAdd(&cnt[0], xf); atomicAdd(&cnt[1], xi);
    atomicAdd(&cnt[2], wf); atomicAdd(&cnt[3], wi);

    int bf = 0, bh = 0;
    for (int i = tid; i < 384; i += 256) {
        uint32_t u = b[i];
        float f = __uint_as_float(u);
        if (isfinite(f) && (f == 0.f || (fabsf(f) >= 1e-6f && fabsf(f) <= 100.f))) bf++;
        float h0 = __half2float(__ushort_as_half((unsigned short)(u & 0xFFFF)));
        float h1 = __half2float(__ushort_as_half((unsigned short)(u >> 16)));
        if (isfinite(h0) && fabsf(h0) <= 100.f && isfinite(h1) && fabsf(h1) <= 100.f) bh++;
    }
    atomicAdd(&cnt[4], bf); atomicAdd(&cnt[5], bh);
    __syncthreads();

    if (tid == 0) {
        g_modes[0] = (cnt[0] >= 3686) ? 0 : ((cnt[1] >= 3686) ? 1 : 2);
        g_modes[1] = (cnt[2] >= 3686) ? 0 : ((cnt[3] >= 3686) ? 1 : 2);
        g_modes[2] = (cnt[4] >= 346)  ? 0 : 1;
    }
}

// ===========================================================================
// helpers
// ===========================================================================
__device__ __forceinline__ int swz(int row, int w) {
    return row * 16 + (w ^ (((row >> 1) & 3) << 2));
}

__device__ __forceinline__ float quantf(int acc, float alpha, float b) {
    float v = __fadd_rn(__fmul_rn((float)acc, alpha), b);
    float f = rintf(v);
    return fminf(fmaxf(f, -128.f), 127.f);
}

__device__ __forceinline__ void load_stage(uint32_t sbase, int m0, int n0,
                                           int s, int kt, int tid) {
    const uint32_t sa = sbase + (uint32_t)s * STG_BYTES;
    const uint32_t sb = sa + BM * BK;
    const int8_t* gA = g_X8 + (size_t)m0 * KD + kt * BK;
    const int8_t* gB = g_Wt + (size_t)n0 * KD + kt * BK;
#pragma unroll
    for (int i = 0; i < 2; i++) {
        const int id = tid * 2 + i;            // 0..511
        const int row = id >> 2;               // 0..127
        const int c = id & 3;                  // 16B chunk within 64B row
        const uint32_t off = 4u * swz(row, c * 4);
        asm volatile("cp.async.cg.shared.global [%0], [%1], 16;"
                     :: "r"(sa + off), "l"(gA + (size_t)row * KD + c * 16));
        asm volatile("cp.async.cg.shared.global [%0], [%1], 16;"
                     :: "r"(sb + off), "l"(gB + (size_t)row * KD + c * 16));
    }
    asm volatile("cp.async.commit_group;" ::: "memory");
}

// ===========================================================================
// Mega kernel: bids [0, NCONV) = producer role (W transpose + x convert),
// bids [NCONV, NCONV + M/BM*6) = GEMM role gated on flags.
// ===========================================================================
__global__ __launch_bounds__(256, 2)
void mega(const void* __restrict__ xp, const void* __restrict__ wp,
          const void* __restrict__ bias_p, const float* __restrict__ alpha_p,
          float* __restrict__ out, int M) {
    __shared__ int8_t smem[NSTG * STG_BYTES];  // 48 KB
    const int tid = threadIdx.x;
    const int nchunk = M / BM;

    // ------------------------------- producer -------------------------------
    if (blockIdx.x < NCONV) {
        const int cid = blockIdx.x;

        // 1) weight tiles (32x32 transpose via smem)
        const int wmode = g_modes[1];
        int8_t (*t)[33] = reinterpret_cast<int8_t(*)[33]>(smem);
        const int tx = tid & 31, ty = tid >> 5;   // 32 x 8
        int my_tiles = 0;
        for (int tl = cid; tl < WTILES; tl += NCONV) {
            const int nb = (tl % (ND / 32)) * 32;
            const int kb = (tl / (ND / 32)) * 32;
            __syncthreads();
#pragma unroll
            for (int j = 0; j < 32; j += 8) {
                const int kk = kb + ty + j, nn = nb + tx;
                int8_t v;
                if (wmode == 0)      v = (int8_t)__float2int_rn(((const float*)wp)[kk * ND + nn]);
                else if (wmode == 1) v = (int8_t)(((const int*)wp)[kk * ND + nn]);
                else                 v = ((const int8_t*)wp)[kk * ND + nn];
                t[ty + j][tx] = v;
            }
            __syncthreads();
#pragma unroll
            for (int j = 0; j < 32; j += 8)
                g_Wt[(size_t)(nb + ty + j) * KD + kb + tx] = t[tx][ty + j];
            my_tiles++;
        }
        __threadfence();
        __syncthreads();
        if (tid == 0 && my_tiles) atomicAdd(&g_wcnt, my_tiles);

        // 2) x chunks (128 rows each), own chunk first, then strided
        const int xmode = g_modes[0];
        for (int ch = cid; ch < nchunk; ch += NCONV) {
            const size_t base = (size_t)ch * BM * KD;
#pragma unroll 1
            for (int it = 0; it < (BM * KD) / (256 * 16); it++) {
                const size_t idx = base + ((size_t)it * 256 + tid) * 16;
                if (xmode == 2) {
                    *reinterpret_cast<int4*>(&g_X8[idx]) =
                        *reinterpret_cast<const int4*>((const int8_t*)xp + idx);
                } else if (xmode == 0) {
                    const float* f = (const float*)xp + idx;
                    int8_t o[16];
#pragma unroll
                    for (int j = 0; j < 16; j += 4) {
                        float4 v = *reinterpret_cast<const float4*>(f + j);
                        o[j + 0] = (int8_t)__float2int_rn(v.x);
                        o[j + 1] = (int8_t)__float2int_rn(v.y);
                        o[j + 2] = (int8_t)__float2int_rn(v.z);
                        o[j + 3] = (int8_t)__float2int_rn(v.w);
                    }
                    *reinterpret_cast<int4*>(&g_X8[idx]) = *reinterpret_cast<int4*>(o);
                } else {
                    const int* f = (const int*)xp + idx;
                    int8_t o[16];
#pragma unroll
                    for (int j = 0; j < 16; j += 4) {
                        int4 v = *reinterpret_cast<const int4*>(f + j);
                        o[j + 0] = (int8_t)v.x; o[j + 1] = (int8_t)v.y;
                        o[j + 2] = (int8_t)v.z; o[j + 3] = (int8_t)v.w;
                    }
                    *reinterpret_cast<int4*>(&g_X8[idx]) = *reinterpret_cast<int4*>(o);
                }
            }
            __threadfence();
            __syncthreads();
            if (tid == 0) st_rel(&g_flag[ch], 1);
        }
        return;
    }

    // -------------------------------- GEMM ----------------------------------
    const int bid  = blockIdx.x - NCONV;
    const int n0   = (bid % NBLK_N) * BN;
    const int mblk = bid / NBLK_N;
    const int m0   = mblk * BM;

    if (tid == 0) {
        while (ld_acq(&g_wcnt) < WTILES) __nanosleep(128);
        while (ld_acq(&g_flag[mblk]) == 0) __nanosleep(128);
    }
    __syncthreads();

    const uint32_t sbase = (uint32_t)__cvta_generic_to_shared(smem);
    const int lane = tid & 31;
    const int warp = tid >> 5;
    const int wm = warp & 1;                   // 2 warps along M (64 rows)
    const int wn = warp >> 1;                  // 4 warps along N (32 cols)
    const int r = lane >> 2;
    const int q = lane & 3;

    const int j  = lane & 7;
    const int mg = lane >> 3;
    uint32_t offA[4][2], offB[2][2];
#pragma unroll
    for (int mt = 0; mt < 4; mt++) {
        const int rowA = wm * 64 + mt * 16 + (mg & 1) * 8 + j;
#pragma unroll
        for (int ks = 0; ks < 2; ks++)
            offA[mt][ks] = 4u * swz(rowA, ks * 8 + (mg >> 1) * 4);
    }
#pragma unroll
    for (int p = 0; p < 2; p++) {
        const int rowB = wn * 32 + p * 16 + (mg >> 1) * 8 + j;
#pragma unroll
        for (int ks = 0; ks < 2; ks++)
            offB[p][ks] = 4u * swz(rowB, ks * 8 + (mg & 1) * 4);
    }

    int acc[4][4][4];
#pragma unroll
    for (int i = 0; i < 4; i++)
#pragma unroll
        for (int jj = 0; jj < 4; jj++)
#pragma unroll
            for (int k = 0; k < 4; k++) acc[i][jj][k] = 0;

    load_stage(sbase, m0, n0, 0, 0, tid);
    load_stage(sbase, m0, n0, 1, 1, tid);

#pragma unroll
    for (int kt = 0; kt < KTILES; kt++) {
        if (kt < KTILES - 1) asm volatile("cp.async.wait_group 1;" ::: "memory");
        else                 asm volatile("cp.async.wait_group 0;" ::: "memory");
        __syncthreads();

        if (kt + 2 < KTILES)
            load_stage(sbase, m0, n0, (kt + 2) % NSTG, kt + 2, tid);

        const uint32_t aB = sbase + (uint32_t)(kt % NSTG) * STG_BYTES;
        const uint32_t bB = aB + BM * BK;

#pragma unroll
        for (int ks = 0; ks < 2; ks++) {
            uint32_t af[4][4], bf[4][2];
#pragma unroll
            for (int mt = 0; mt < 4; mt++)
                asm volatile(
                    "ldmatrix.sync.aligned.m8n8.x4.shared.b16 {%0,%1,%2,%3}, [%4];"
                    : "=r"(af[mt][0]), "=r"(af[mt][1]),
                      "=r"(af[mt][2]), "=r"(af[mt][3])
                    : "r"(aB + offA[mt][ks]));
#pragma unroll
            for (int p = 0; p < 2; p++)
                asm volatile(
                    "ldmatrix.sync.aligned.m8n8.x4.shared.b16 {%0,%1,%2,%3}, [%4];"
                    : "=r"(bf[2 * p][0]), "=r"(bf[2 * p][1]),
                      "=r"(bf[2 * p + 1][0]), "=r"(bf[2 * p + 1][1])
                    : "r"(bB + offB[p][ks]));
#pragma unroll
            for (int mt = 0; mt < 4; mt++)
#pragma unroll
                for (int nt = 0; nt < 4; nt++) {
                    asm volatile(
                        "mma.sync.aligned.m16n8k32.row.col.s32.s8.s8.s32 "
                        "{%0,%1,%2,%3}, {%4,%5,%6,%7}, {%8,%9}, {%0,%1,%2,%3};"
                        : "+r"(acc[mt][nt][0]), "+r"(acc[mt][nt][1]),
                          "+r"(acc[mt][nt][2]), "+r"(acc[mt][nt][3])
                        : "r"(af[mt][0]), "r"(af[mt][1]),
                          "r"(af[mt][2]), "r"(af[mt][3]),
                          "r"(bf[nt][0]), "r"(bf[nt][1]));
                }
        }
    }

    const float alpha = *alpha_p;
    const int bmode = g_modes[2];
#pragma unroll
    for (int mt = 0; mt < 4; mt++) {
        const int row = m0 + wm * 64 + mt * 16 + r;
#pragma unroll
        for (int nt = 0; nt < 4; nt++) {
            const int col = n0 + wn * 32 + nt * 8 + q * 2;
            float b0, b1;
            if (bmode == 0) {
                b0 = ((const float*)bias_p)[col];
                b1 = ((const float*)bias_p)[col + 1];
            } else {
                b0 = __half2float(((const __half*)bias_p)[col]);
                b1 = __half2float(((const __half*)bias_p)[col + 1]);
            }
            float2 v0, v1;
            v0.x = quantf(acc[mt][nt][0], alpha, b0);
            v0.y = quantf(acc[mt][nt][1], alpha, b1);
            v1.x = quantf(acc[mt][nt][2], alpha, b0);
            v1.y = quantf(acc[mt][nt][3], alpha, b1);
            *reinterpret_cast<float2*>(out + (size_t)row * ND + col)       = v0;
            *reinterpret_cast<float2*>(out + (size_t)(row + 8) * ND + col) = v1;
        }
    }
}

// ===========================================================================
extern "C" void kernel_launch(void* const* d_in, const int* in_sizes, int n_in,
                              void* d_out, int out_size) {
    const void* x     = d_in[0];
    const void* w     = d_in[1];
    const void* bias  = d_in[2];
    const float* alpha = (const float*)d_in[3];
    float* out = (float*)d_out;

    const int M = in_sizes[0] / KD;              // 32768

    detect<<<1, 256>>>((const uint32_t*)x, (const uint32_t*)w, (const uint32_t*)bias);

    const unsigned nblocks = NCONV + (unsigned)(M / BM) * NBLK_N;
    mega<<<nblocks, 256>>>(x, w, bias, alpha, out, M);
}

// round 9
// speedup vs baseline: 1.0803x; 1.0803x over previous
#include <cuda_runtime.h>
#include <cuda_fp16.h>
#include <stdint.h>

#define KD 768
#define ND 768
#define MMAX 32768

#define BM 128
#define BN 128
#define BK 64
#define KTILES (KD / BK)                // 12
#define NSTG 3
#define STG_BYTES (BM * BK + BN * BK)   // 16384

// Scratch (device globals — no runtime allocation).
__device__ int8_t g_X8[(size_t)MMAX * KD];
__device__ int8_t g_Wt[ND * KD];
__device__ int    g_modes[3];

// ===========================================================================
// dtype detection (x/w: 0=f32-of-ints, 1=int32, 2=int8; bias: 0=f32, 1=f16)
// ===========================================================================
__device__ __forceinline__ bool ok_f32_int(uint32_t u) {
    float f = __uint_as_float(u);
    return isfinite(f) && f == rintf(f) && fabsf(f) <= 127.f;
}
__device__ __forceinline__ bool ok_i32(uint32_t u) {
    int v = (int)u;
    return v >= -128 && v <= 127;
}

__global__ void detect(const uint32_t* __restrict__ x,
                       const uint32_t* __restrict__ w,
                       const uint32_t* __restrict__ b) {
    __shared__ int cnt[6];
    const int tid = threadIdx.x;
    if (tid < 6) cnt[tid] = 0;
    __syncthreads();

    int xf = 0, xi = 0, wf = 0, wi = 0;
#pragma unroll 4
    for (int i = 0; i < 16; i++) {
        uint32_t ux = x[tid * 16 + i];
        uint32_t uw = w[tid * 16 + i];
        xf += ok_f32_int(ux);  xi += ok_i32(ux);
        wf += ok_f32_int(uw);  wi += ok_i32(uw);
    }
    atomicAdd(&cnt[0], xf); atomicAdd(&cnt[1], xi);
    atomicAdd(&cnt[2], wf); atomicAdd(&cnt[3], wi);

    int bf = 0, bh = 0;
    for (int i = tid; i < 384; i += 256) {
        uint32_t u = b[i];
        float f = __uint_as_float(u);
        if (isfinite(f) && (f == 0.f || (fabsf(f) >= 1e-6f && fabsf(f) <= 100.f))) bf++;
        float h0 = __half2float(__ushort_as_half((unsigned short)(u & 0xFFFF)));
        float h1 = __half2float(__ushort_as_half((unsigned short)(u >> 16)));
        if (isfinite(h0) && fabsf(h0) <= 100.f && isfinite(h1) && fabsf(h1) <= 100.f) bh++;
    }
    atomicAdd(&cnt[4], bf); atomicAdd(&cnt[5], bh);
    __syncthreads();

    if (tid == 0) {
        g_modes[0] = (cnt[0] >= 3686) ? 0 : ((cnt[1] >= 3686) ? 1 : 2);
        g_modes[1] = (cnt[2] >= 3686) ? 0 : ((cnt[3] >= 3686) ? 1 : 2);
        g_modes[2] = (cnt[4] >= 346)  ? 0 : 1;
    }
}

// ===========================================================================
// Normalize x -> g_X8 (int8). 16 elements per thread.
// ===========================================================================
__global__ void conv_x(const void* __restrict__ xp, int M) {
    const int mode = g_modes[0];
    const size_t n = (size_t)M * KD;
    const size_t idx = ((size_t)blockIdx.x * blockDim.x + threadIdx.x) * 16;
    if (idx >= n) return;

    if (mode == 2) {
        *reinterpret_cast<int4*>(&g_X8[idx]) =
            *reinterpret_cast<const int4*>((const int8_t*)xp + idx);
        return;
    }
    int8_t o[16];
    if (mode == 0) {
        const float* f = (const float*)xp + idx;
#pragma unroll
        for (int j = 0; j < 16; j += 4) {
            float4 v = *reinterpret_cast<const float4*>(f + j);
            o[j + 0] = (int8_t)__float2int_rn(v.x);
            o[j + 1] = (int8_t)__float2int_rn(v.y);
            o[j + 2] = (int8_t)__float2int_rn(v.z);
            o[j + 3] = (int8_t)__float2int_rn(v.w);
        }
    } else {
        const int* f = (const int*)xp + idx;
#pragma unroll
        for (int j = 0; j < 16; j += 4) {
            int4 v = *reinterpret_cast<const int4*>(f + j);
            o[j + 0] = (int8_t)v.x; o[j + 1] = (int8_t)v.y;
            o[j + 2] = (int8_t)v.z; o[j + 3] = (int8_t)v.w;
        }
    }
    *reinterpret_cast<int4*>(&g_X8[idx]) = *reinterpret_cast<int4*>(o);
}

// ===========================================================================
// Weight: W[k][n] (any mode) -> g_Wt[n][k] int8
// ===========================================================================
__global__ void wt_prep(const void* __restrict__ wp) {
    const int mode = g_modes[1];
    __shared__ int8_t t[32][33];
    const int nb = blockIdx.x * 32, kb = blockIdx.y * 32;
    const int tx = threadIdx.x, ty = threadIdx.y;
#pragma unroll
    for (int j = 0; j < 32; j += 8) {
        const int kk = kb + ty + j, nn = nb + tx;
        int8_t v;
        if (mode == 0)      v = (int8_t)__float2int_rn(((const float*)wp)[kk * ND + nn]);
        else if (mode == 1) v = (int8_t)(((const int*)wp)[kk * ND + nn]);
        else                v = ((const int8_t*)wp)[kk * ND + nn];
        t[ty + j][tx] = v;
    }
    __syncthreads();
#pragma unroll
    for (int j = 0; j < 32; j += 8)
        g_Wt[(nb + ty + j) * KD + kb + tx] = t[tx][ty + j];
}

// ===========================================================================
// helpers
// ===========================================================================
__device__ __forceinline__ int swz(int row, int w) {
    return row * 16 + (w ^ (((row >> 1) & 3) << 2));
}

__device__ __forceinline__ float quantf(int acc, float alpha, float b) {
    float v = __fadd_rn(__fmul_rn((float)acc, alpha), b);
    float f = rintf(v);
    return fminf(fmaxf(f, -128.f), 127.f);
}

#define LDSM4(r0, r1, r2, r3, addr) \
    asm volatile("ldmatrix.sync.aligned.m8n8.x4.shared.b16 {%0,%1,%2,%3}, [%4];" \
                 : "=r"(r0), "=r"(r1), "=r"(r2), "=r"(r3) : "r"(addr))

#define MMA_ROW(accrow, a, bfr)                                               \
    do {                                                                      \
        _Pragma("unroll")                                                     \
        for (int nt = 0; nt < 4; nt++) {                                      \
            asm volatile(                                                     \
                "mma.sync.aligned.m16n8k32.row.col.s32.s8.s8.s32 "            \
                "{%0,%1,%2,%3}, {%4,%5,%6,%7}, {%8,%9}, {%0,%1,%2,%3};"       \
                : "+r"((accrow)[nt][0]), "+r"((accrow)[nt][1]),               \
                  "+r"((accrow)[nt][2]), "+r"((accrow)[nt][3])                \
                : "r"((a)[0]), "r"((a)[1]), "r"((a)[2]), "r"((a)[3]),         \
                  "r"((bfr)[nt][0]), "r"((bfr)[nt][1]));                      \
        }                                                                     \
    } while (0)

// ===========================================================================
// GEMM: 128x128x64 tiles, 8 warps (2x4), 3-stage cp.async, software-pipelined
// ldmatrix fragments (ping-pong A, double-buffered B), mma.m16n8k32.s8.
// ===========================================================================
__device__ __forceinline__ void load_stage(uint32_t sbase, int m0, int n0,
                                           int s, int kt, int tid) {
    const uint32_t sa = sbase + (uint32_t)s * STG_BYTES;
    const uint32_t sb = sa + BM * BK;
    const int8_t* gA = g_X8 + (size_t)m0 * KD + kt * BK;
    const int8_t* gB = g_Wt + (size_t)n0 * KD + kt * BK;
#pragma unroll
    for (int i = 0; i < 2; i++) {
        const int id = tid * 2 + i;            // 0..511
        const int row = id >> 2;               // 0..127
        const int c = id & 3;                  // 16B chunk within 64B row
        const uint32_t off = 4u * swz(row, c * 4);
        asm volatile("cp.async.cg.shared.global [%0], [%1], 16;"
                     :: "r"(sa + off), "l"(gA + (size_t)row * KD + c * 16));
        asm volatile("cp.async.cg.shared.global [%0], [%1], 16;"
                     :: "r"(sb + off), "l"(gB + (size_t)row * KD + c * 16));
    }
    asm volatile("cp.async.commit_group;" ::: "memory");
}

__global__ __launch_bounds__(256, 2)
void gemm_q8(const void* __restrict__ bias_p, const float* __restrict__ alpha_p,
             float* __restrict__ out) {
    __shared__ int8_t smem[NSTG * STG_BYTES];  // 48 KB
    const uint32_t sbase = (uint32_t)__cvta_generic_to_shared(smem);

    const int tid  = threadIdx.x;
    const int lane = tid & 31;
    const int warp = tid >> 5;
    const int wm = warp & 1;                   // 2 warps along M (64 rows)
    const int wn = warp >> 1;                  // 4 warps along N (32 cols)
    const int m0 = blockIdx.y * BM;
    const int n0 = blockIdx.x * BN;
    const int r = lane >> 2;
    const int q = lane & 3;

    // Per-lane swizzled ldmatrix offsets (reused every k-tile).
    const int j  = lane & 7;
    const int mg = lane >> 3;
    uint32_t offA[4][2], offB[2][2];
#pragma unroll
    for (int mt = 0; mt < 4; mt++) {
        const int rowA = wm * 64 + mt * 16 + (mg & 1) * 8 + j;
#pragma unroll
        for (int ks = 0; ks < 2; ks++)
            offA[mt][ks] = 4u * swz(rowA, ks * 8 + (mg >> 1) * 4);
    }
#pragma unroll
    for (int p = 0; p < 2; p++) {
        const int rowB = wn * 32 + p * 16 + (mg >> 1) * 8 + j;
#pragma unroll
        for (int ks = 0; ks < 2; ks++)
            offB[p][ks] = 4u * swz(rowB, ks * 8 + (mg & 1) * 4);
    }

    int acc[4][4][4];
#pragma unroll
    for (int i = 0; i < 4; i++)
#pragma unroll
        for (int jj = 0; jj < 4; jj++)
#pragma unroll
            for (int k = 0; k < 4; k++) acc[i][jj][k] = 0;

    load_stage(sbase, m0, n0, 0, 0, tid);
    load_stage(sbase, m0, n0, 1, 1, tid);

    uint32_t af[2][4];                 // ping-pong A fragments (one m-row each)
    uint32_t bf0[4][2], bf1[4][2];     // B fragments for ks=0 / ks=1

#pragma unroll
    for (int kt = 0; kt < KTILES; kt++) {
        if (kt < KTILES - 1) asm volatile("cp.async.wait_group 1;" ::: "memory");
        else                 asm volatile("cp.async.wait_group 0;" ::: "memory");
        __syncthreads();

        if (kt + 2 < KTILES)
            load_stage(sbase, m0, n0, (kt + 2) % NSTG, kt + 2, tid);

        const uint32_t aB = sbase + (uint32_t)(kt % NSTG) * STG_BYTES;
        const uint32_t bB = aB + BM * BK;

        // ---- k-tile head: ks=0 B fragments + first A row ----
        LDSM4(bf0[0][0], bf0[0][1], bf0[1][0], bf0[1][1], bB + offB[0][0]);
        LDSM4(bf0[2][0], bf0[2][1], bf0[3][0], bf0[3][1], bB + offB[1][0]);
        LDSM4(af[0][0], af[0][1], af[0][2], af[0][3],     aB + offA[0][0]);

        // ---- ks = 0: prefetch next row / next-ks frags before each MMA row --
        LDSM4(af[1][0], af[1][1], af[1][2], af[1][3], aB + offA[1][0]);
        MMA_ROW(acc[0], af[0], bf0);
        LDSM4(af[0][0], af[0][1], af[0][2], af[0][3], aB + offA[2][0]);
        MMA_ROW(acc[1], af[1], bf0);
        LDSM4(af[1][0], af[1][1], af[1][2], af[1][3], aB + offA[3][0]);
        MMA_ROW(acc[2], af[0], bf0);
        LDSM4(bf1[0][0], bf1[0][1], bf1[1][0], bf1[1][1], bB + offB[0][1]);
        LDSM4(bf1[2][0], bf1[2][1], bf1[3][0], bf1[3][1], bB + offB[1][1]);
        LDSM4(af[0][0], af[0][1], af[0][2], af[0][3],     aB + offA[0][1]);
        MMA_ROW(acc[3], af[1], bf0);

        // ---- ks = 1 ----
        LDSM4(af[1][0], af[1][1], af[1][2], af[1][3], aB + offA[1][1]);
        MMA_ROW(acc[0], af[0], bf1);
        LDSM4(af[0][0], af[0][1], af[0][2], af[0][3], aB + offA[2][1]);
        MMA_ROW(acc[1], af[1], bf1);
        LDSM4(af[1][0], af[1][1], af[1][2], af[1][3], aB + offA[3][1]);
        MMA_ROW(acc[2], af[0], bf1);
        MMA_ROW(acc[3], af[1], bf1);
    }

    // epilogue: dequant + bias + round-half-even + clamp, fp32 stores
    const float alpha = *alpha_p;
    const int bmode = g_modes[2];
#pragma unroll
    for (int mt = 0; mt < 4; mt++) {
        const int row = m0 + wm * 64 + mt * 16 + r;
#pragma unroll
        for (int nt = 0; nt < 4; nt++) {
            const int col = n0 + wn * 32 + nt * 8 + q * 2;
            float b0, b1;
            if (bmode == 0) {
                b0 = ((const float*)bias_p)[col];
                b1 = ((const float*)bias_p)[col + 1];
            } else {
                b0 = __half2float(((const __half*)bias_p)[col]);
                b1 = __half2float(((const __half*)bias_p)[col + 1]);
            }
            float2 v0, v1;
            v0.x = quantf(acc[mt][nt][0], alpha, b0);
            v0.y = quantf(acc[mt][nt][1], alpha, b1);
            v1.x = quantf(acc[mt][nt][2], alpha, b0);
            v1.y = quantf(acc[mt][nt][3], alpha, b1);
            *reinterpret_cast<float2*>(out + (size_t)row * ND + col)       = v0;
            *reinterpret_cast<float2*>(out + (size_t)(row + 8) * ND + col) = v1;
        }
    }
}

// ===========================================================================
extern "C" void kernel_launch(void* const* d_in, const int* in_sizes, int n_in,
                              void* d_out, int out_size) {
    const void* x     = d_in[0];
    const void* w     = d_in[1];
    const void* bias  = d_in[2];
    const float* alpha = (const float*)d_in[3];
    float* out = (float*)d_out;

    const int M = in_sizes[0] / KD;

    detect<<<1, 256>>>((const uint32_t*)x, (const uint32_t*)w, (const uint32_t*)bias);

    const size_t n = (size_t)M * KD;
    conv_x<<<(unsigned)((n / 16 + 255) / 256), 256>>>(x, M);
    wt_prep<<<dim3(ND / 32, KD / 32), dim3(32, 8)>>>(w);

    gemm_q8<<<dim3(ND / BN, M / BM), 256>>>(bias, alpha, out);
}